// round 6
// baseline (speedup 1.0000x reference)
#include <cuda_runtime.h>
#include <cstdint>

// ---------------------------------------------------------------------------
// SpikeFP32Embedding: out[tok] = weight_pulse[token_ids[tok]]
//   token_ids   : [16384]  (int64 per reference; int32 if JAX x64 was off)
//   weight_pulse: [32768, 128, 32] fp32  -> 16 KB per row
//   out         : [16384, 128, 32] fp32
// Pure row gather, memory-bound. Traffic at floor (~210 MB unique reads +
// 256 MB writes). Four prior configs (MLP 4/8, 128/256 thr, WT/CS stores)
// all plateau at 76.5-77.2 us / ~6.05 TB/s.
//
// R6 experiment (last unexplored axis): 256-bit global accesses
// (sm_100a v8.f32 ld/st) — halves L1tex wavefronts per warp-instruction and
// gives the DRAM scheduler 1024B-contiguous requests per warp.
// ---------------------------------------------------------------------------

#define ROW_V8   512    // 128*32 floats = 4096 floats = 512 x 8-float chunks
#define THREADS  256
#define V8_PER_T (ROW_V8 / THREADS)   // 2

struct __align__(32) f32x8 { float v[8]; };

__device__ __forceinline__ f32x8 ldg256(const f32x8* p) {
    f32x8 r;
    asm volatile(
        "ld.global.nc.v8.f32 {%0,%1,%2,%3,%4,%5,%6,%7}, [%8];"
        : "=f"(r.v[0]), "=f"(r.v[1]), "=f"(r.v[2]), "=f"(r.v[3]),
          "=f"(r.v[4]), "=f"(r.v[5]), "=f"(r.v[6]), "=f"(r.v[7])
        : "l"(p));
    return r;
}

__device__ __forceinline__ void stg256_cs(f32x8* p, const f32x8& r) {
    asm volatile(
        "st.global.cs.v8.f32 [%8], {%0,%1,%2,%3,%4,%5,%6,%7};"
        :: "f"(r.v[0]), "f"(r.v[1]), "f"(r.v[2]), "f"(r.v[3]),
           "f"(r.v[4]), "f"(r.v[5]), "f"(r.v[6]), "f"(r.v[7]),
           "l"(p)
        : "memory");
}

__global__ __launch_bounds__(THREADS)
void gather_rows_kernel(const void* __restrict__ ids,
                        const f32x8* __restrict__ w,
                        f32x8* __restrict__ out) {
    // ---- per-warp inline dtype detection ------------------------------------
    // u64 words 1..8 of the id buffer: under int64 layout these are tokens
    // 1..8 (< 2^15); under int32 packing any nonzero token at odd index 3..17
    // makes a word >= 2^32. 8 parallel broadcast loads (L2-hit after the
    // first warp) + one ballot. False-negative prob ~ (1/32000)^8.
    const int lane = threadIdx.x & 31;
    bool hi = false;
    if (lane >= 1 && lane <= 8)
        hi = (__ldg((const unsigned long long*)ids + lane) >= 32768ULL);
    const bool ids_i64 = !__any_sync(0xffffffffu, hi);

    // ---- row gather ----------------------------------------------------------
    const int tok = blockIdx.x;

    long long id;
    if (ids_i64) {
        id = __ldg((const long long*)ids + tok);
    } else {
        id = (long long)__ldg((const int*)ids + tok);
    }

    const f32x8* __restrict__ src = w   + (size_t)id  * ROW_V8;
    f32x8*       __restrict__ dst = out + (size_t)tok * ROW_V8;

    const int t = threadIdx.x;

    // Front-batch the independent 256-bit loads, then drain stores.
    f32x8 a = ldg256(&src[t]);
    f32x8 b = ldg256(&src[t + THREADS]);
    stg256_cs(&dst[t],           a);
    stg256_cs(&dst[t + THREADS], b);
}

extern "C" void kernel_launch(void* const* d_in, const int* in_sizes, int n_in,
                              void* d_out, int out_size) {
    const void*  ids = d_in[0];
    const f32x8* w   = (const f32x8*)d_in[1];
    f32x8*       out = (f32x8*)d_out;

    const int n_tokens = in_sizes[0];   // 16384

    gather_rows_kernel<<<n_tokens, THREADS>>>(ids, w, out);
}